// round 15
// baseline (speedup 1.0000x reference)
#include <cuda_runtime.h>
#include <math.h>

#define CIN 256
#define NCLS 91
#define NANC 9
#define TOPKN 1000
#define DETSN 300
#define CAP 16384
#define SCAP 8192
#define NEGV -1e9f
#define BBOX_CLIP 4.135166556742356f
#define IMGSZ 512.0f

typedef unsigned long long ull;

// ---------------- scratch layout (float units) ----------------
#define OFF_WT_CT 0ull
#define OFF_WT_RT 2359296ull
#define OFF_WT_CL 4718592ull
#define OFF_WT_RB 6782976ull
#define OFF_BUFA  7077888ull
#define OFF_BUFB  8474624ull
#define OFF_BUFC  9871360ull
#define OFF_BUFD  11268096ull
#define OFF_LOG   12664832ull
#define OFF_REG   17133296ull
#define OFF_KEYS  17329712ull
#define OFF_CK    21798176ull
#define OFF_CI    21880096ull
#define OFF_SLS   21962016ull
#define OFF_SLI   21967016ull
#define OFF_CS    21972016ull
#define OFF_CB    21977016ull
#define OFF_CL2   21997016ull
#define TOTAL_F   22002016ull

__device__ __align__(16) float g_scratch[TOTAL_F];

struct SelState {
    int cnt, slotn, fillmode, b1, k2;
    unsigned T;
    int hist1[2048];
    int hist2[2048];
};
__device__ SelState d_st[5];
__device__ int g_gmax;

// level constants
__constant__ int c_NL[5]    = {3354624, 838656, 209664, 52416, 13104};
__constant__ int c_KB[5]    = {0, 3354624, 4193280, 4402944, 4455360};
__constant__ int c_cumHW[5] = {0, 4096, 5120, 5376, 5440};
__constant__ int c_HW[5]    = {4096, 1024, 256, 64, 16};
__constant__ int c_logHW[5] = {12, 10, 8, 6, 4};

// ------------- packed f32x2 helpers -------------
__device__ __forceinline__ ull pk2(float lo, float hi) {
    ull r;
    asm("mov.b64 %0,{%1,%2};" : "=l"(r) : "f"(lo), "f"(hi));
    return r;
}
__device__ __forceinline__ void unpk2(ull v, float& lo, float& hi) {
    asm("mov.b64 {%0,%1},%2;" : "=f"(lo), "=f"(hi) : "l"(v));
}
__device__ __forceinline__ void ffma2(ull& d, ull a, ull b) {
    asm("fma.rn.f32x2 %0,%1,%2,%0;" : "+l"(d) : "l"(a), "l"(b));
}

// ------------- coalesced-write weight transpose: OIHW -> wT[k_lin][CoutPad] -------------
__global__ void transpose_all(const float* __restrict__ ctw, const float* __restrict__ rtw,
                              const float* __restrict__ cow, const float* __restrict__ rbw) {
    float* S = g_scratch;
    const int TN = 589824;
    long long g = (long long)blockIdx.x * blockDim.x + threadIdx.x;
    if (g < 262144) {
        int sub = (int)(g >> 16);
        int r = (int)(g & 65535);
        int ic = r >> 8, oc = r & 255;
        const float* src = ctw + (size_t)sub * TN + (size_t)oc * 2304 + ic * 9;
        float* dst = S + OFF_WT_CT + (size_t)sub * TN + (size_t)ic * 256 + oc;
#pragma unroll
        for (int tap = 0; tap < 9; tap++) dst[(size_t)tap * 65536] = src[tap];
    } else if (g < 524288) {
        g -= 262144;
        int sub = (int)(g >> 16);
        int r = (int)(g & 65535);
        int ic = r >> 8, oc = r & 255;
        const float* src = rtw + (size_t)sub * TN + (size_t)oc * 2304 + ic * 9;
        float* dst = S + OFF_WT_RT + (size_t)sub * TN + (size_t)ic * 256 + oc;
#pragma unroll
        for (int tap = 0; tap < 9; tap++) dst[(size_t)tap * 65536] = src[tap];
    } else if (g < 753664) {
        int r = (int)(g - 524288);
        int ic = r / 896, oc = r % 896;
        float* dst = S + OFF_WT_CL + (size_t)ic * 896 + oc;
        if (oc < 819) {
            const float* src = cow + (size_t)oc * 2304 + ic * 9;
#pragma unroll
            for (int tap = 0; tap < 9; tap++) dst[(size_t)tap * 229376] = src[tap];
        } else {
#pragma unroll
            for (int tap = 0; tap < 9; tap++) dst[(size_t)tap * 229376] = 0.f;
        }
    } else if (g < 786432) {
        int r = (int)(g - 753664);
        int ic = r >> 7, oc = r & 127;
        float* dst = S + OFF_WT_RB + (size_t)ic * 128 + oc;
        if (oc < 36) {
            const float* src = rbw + (size_t)oc * 2304 + ic * 9;
#pragma unroll
            for (int tap = 0; tap < 9; tap++) dst[(size_t)tap * 32768] = src[tap];
        } else {
#pragma unroll
            for (int tap = 0; tap < 9; tap++) dst[(size_t)tap * 32768] = 0.f;
        }
    }
}

// ------------- zero all selection state -------------
__global__ void zero_all() {
    int t = blockIdx.x * blockDim.x + threadIdx.x;
    if (t < 5 * 2048) {
        int l = t / 2048, e = t % 2048;
        d_st[l].hist1[e] = 0;
        d_st[l].hist2[e] = 0;
    }
    if (t < 5) {
        d_st[t].cnt = 0; d_st[t].slotn = 0; d_st[t].fillmode = 0;
        d_st[t].b1 = -1; d_st[t].k2 = 0; d_st[t].T = 0u;
    }
    if (t == 5) g_gmax = 0;
}

// ------------- merged 3x3 SAME conv v4: 32oc x 64px tile, 128 threads,
//               4oc x 4px microtile, fma-bound issue mix (14 issues / 16 fma-cyc) -------------
// gx: 64,16,4,1,1 -> 86
// tower: y 0..7 cls oc-block, 8..15 reg; head: y 0..25 cls, 26..27 reg
__global__ void __launch_bounds__(128, 8) conv_merged(
    const float* __restrict__ f0, const float* __restrict__ f1, const float* __restrict__ f2,
    const float* __restrict__ f3, const float* __restrict__ f4,
    const float* __restrict__ cinBuf, const float* __restrict__ rinBuf,
    const float* __restrict__ wTc, const float* __restrict__ bc, float* __restrict__ coutBuf,
    const float* __restrict__ wTr, const float* __restrict__ br, float* __restrict__ routBuf,
    int stage, int head) {
    __shared__ float As[2][16][32];
    __shared__ float Bs[2][16][64];

    int bx = blockIdx.x;
    int l, gxB;
    if (bx < 64)      { l = 0; gxB = 0; }
    else if (bx < 80) { l = 1; gxB = 64; }
    else if (bx < 84) { l = 2; gxB = 80; }
    else if (bx < 85) { l = 3; gxB = 84; }
    else              { l = 4; gxB = 85; }
    int logW = 6 - l;
    int W = 1 << logW, HW = W * W;
    int cum = c_cumHW[l];
    int pxBase = (bx - gxB) * 64;

    const float* in; const float* wT; const float* bias; float* out;
    int Cout, CoutPad, ocBase, relu;
    int y = blockIdx.y;
    if (!head) {
        relu = 1; Cout = 256; CoutPad = 256;
        ocBase = (y & 7) * 32;
        if ((y >> 3) == 0) {
            wT = wTc; bias = bc; out = coutBuf + (size_t)cum * 256;
            in = cinBuf + (size_t)cum * 256;
        } else {
            wT = wTr; bias = br; out = routBuf + (size_t)cum * 256;
            in = rinBuf + (size_t)cum * 256;
        }
        if (stage == 0)
            in = (l == 0) ? f0 : (l == 1) ? f1 : (l == 2) ? f2 : (l == 3) ? f3 : f4;
    } else {
        relu = 0;
        if (y < 26) {
            ocBase = y * 32; Cout = 819; CoutPad = 896;
            wT = wTc; bias = bc;
            in = cinBuf + (size_t)cum * 256;
            out = coutBuf + (size_t)cum * 819;
        } else {
            ocBase = (y - 26) * 32; Cout = 36; CoutPad = 128;
            wT = wTr; bias = br;
            in = rinBuf + (size_t)cum * 256;
            out = routBuf + (size_t)cum * 36;
        }
    }

    int tid = threadIdx.x;             // 0..127
    int tx = tid & 15, ty = tid >> 4;  // ty 0..7: oc group (4 oc), tx: px group (4 px)

    // fill-phase mapping
    int pxF = tid & 63;
    int kB0 = tid >> 6;                // 0..1: B k rows kB0 + 2i
    int pF = pxBase + pxF;
    int prow = pF >> logW;
    int pcol = pF & (W - 1);
    bool okp = pF < HW;

    // acc[i][j]: oc (ocBase + ty*4 + i) x px pair (pxBase + tx*4 + 2j, +1)
    ull acc[4][2];
#pragma unroll
    for (int i = 0; i < 4; i++) { acc[i][0] = 0ull; acc[i][1] = 0ull; }

    float4 pa;
    float pb[8];

    // incremental fetch state; A: thread t -> k-row t>>3, oc col (t&7)*4
    int tapCur = -1;
    bool okT = false;
    long bcur = 0;
    const float* wptr = wT + (size_t)(tid >> 3) * CoutPad + ocBase + ((tid & 7) << 2);
    const size_t wInc = (size_t)16 * CoutPad;
    const long bInc = (long)16 * HW;

    auto fetch = [&](int c) {
        int tap = c >> 4;
        if (tap != tapCur) {
            tapCur = tap;
            int dy = tap / 3 - 1, dx = tap % 3 - 1;
            int hh = prow + dy, ww = pcol + dx;
            okT = okp && ((unsigned)hh < (unsigned)W) && ((unsigned)ww < (unsigned)W);
            bcur = (long)kB0 * HW + (((long)hh) << logW) + ww;
        }
#pragma unroll
        for (int i = 0; i < 8; i++)
            pb[i] = okT ? in[bcur + (long)2 * i * HW] : 0.f;
        bcur += bInc;
        pa = *(const float4*)(wptr);
        wptr += wInc;
    };
    auto stor = [&](int buf) {
        // flat: thread t writes float4 index t -> row t>>3, col (t&7)*4; conflict-free
        float4* asf = (float4*)&As[buf][0][0];
        asf[tid] = pa;
#pragma unroll
        for (int i = 0; i < 8; i++) Bs[buf][kB0 + 2 * i][pxF] = pb[i];
    };

    fetch(0);
    stor(0);
    __syncthreads();

    const int NC = 144;
    for (int c = 0; c < NC; c++) {
        int buf = c & 1;
        if (c + 1 < NC) fetch(c + 1);
#pragma unroll
        for (int k = 0; k < 16; k++) {
            float4 a = *(const float4*)&As[buf][k][ty << 2];
            ulonglong2 b01 = *(const ulonglong2*)&Bs[buf][k][tx << 2];
            float av[4] = {a.x, a.y, a.z, a.w};
#pragma unroll
            for (int i = 0; i < 4; i++) {
                ull aa = pk2(av[i], av[i]);
                ffma2(acc[i][0], aa, b01.x);
                ffma2(acc[i][1], aa, b01.y);
            }
        }
        if (c + 1 < NC) stor(buf ^ 1);
        __syncthreads();
    }

    int px0 = pxBase + (tx << 2);
#pragma unroll
    for (int i = 0; i < 4; i++) {
        int oc = ocBase + (ty << 2) + i;
        if (oc >= Cout) continue;
        float bvl = bias[oc];
        float v[4];
        unpk2(acc[i][0], v[0], v[1]);
        unpk2(acc[i][1], v[2], v[3]);
#pragma unroll
        for (int j = 0; j < 4; j++) {
            v[j] += bvl;
            if (relu) v[j] = fmaxf(v[j], 0.f);
        }
        float* o = out + (size_t)oc * HW + px0;
        if (px0 + 3 < HW) *(float4*)o = make_float4(v[0], v[1], v[2], v[3]);
        else {
#pragma unroll
            for (int j = 0; j < 4; j++) if (px0 + j < HW) o[j] = v[j];
        }
    }
}

// ------------- fused sigmoid keys + hist1 (memory-order); grid (128, 5) -------------
__global__ void keys_hist1_kernel(const float* __restrict__ LOG, unsigned* __restrict__ keys) {
    __shared__ int h[2048];
    int lvl = blockIdx.y;
    int HW = c_HW[lvl];
    int logHW = c_logHW[lvl];
    int total = 819 << logHW;
    const float* lg0 = LOG + (size_t)c_cumHW[lvl] * 819;
    unsigned* kk = keys + c_KB[lvl];
    for (int i = threadIdx.x; i < 2048; i += blockDim.x) h[i] = 0;
    __syncthreads();
    int stride = gridDim.x * blockDim.x;
    for (int idx = blockIdx.x * blockDim.x + threadIdx.x; idx < total; idx += stride) {
        int ch = idx >> logHW;
        int p = idx & (HW - 1);
        float lg = lg0[idx];
        float s = 1.f / (1.f + expf(-lg));
        unsigned k = (s > 0.05f) ? __float_as_uint(s) : 0u;
        kk[(size_t)p * 819 + ch] = k;
        if (k) atomicAdd(&h[k >> 21], 1);
    }
    __syncthreads();
    for (int i = threadIdx.x; i < 2048; i += blockDim.x)
        if (h[i]) atomicAdd(&d_st[lvl].hist1[i], h[i]);
}

__global__ void hist2_kernel(const unsigned* __restrict__ keys) {
    __shared__ int h[2048];
    int lvl = blockIdx.y;
    int b1 = d_st[lvl].b1;
    if (b1 < 0) return;
    int N = c_NL[lvl];
    const unsigned* kk = keys + c_KB[lvl];
    for (int i = threadIdx.x; i < 2048; i += blockDim.x) h[i] = 0;
    __syncthreads();
    for (int i = blockIdx.x * blockDim.x + threadIdx.x; i < N; i += gridDim.x * blockDim.x) {
        unsigned k = kk[i];
        if (k && (int)(k >> 21) == b1) atomicAdd(&h[(k >> 10) & 2047], 1);
    }
    __syncthreads();
    for (int i = threadIdx.x; i < 2048; i += blockDim.x)
        if (h[i]) atomicAdd(&d_st[lvl].hist2[i], h[i]);
}

// grid (5), 256 threads
__global__ void scan_kernel(int pass) {
    __shared__ int s0[2048], s1[2048];
    SelState* st = &d_st[blockIdx.x];
    if (pass == 1 && st->fillmode) return;
    int* hist = (pass == 0) ? st->hist1 : st->hist2;
    int K = (pass == 0) ? TOPKN : st->k2;
    int t = threadIdx.x;
    for (int i = t; i < 2048; i += 256) s0[i] = hist[i];
    __syncthreads();
    int* src = s0; int* dst = s1;
    for (int d = 1; d < 2048; d <<= 1) {
        for (int i = t; i < 2048; i += 256)
            dst[i] = src[i] + ((i + d < 2048) ? src[i + d] : 0);
        __syncthreads();
        int* tmp = src; src = dst; dst = tmp;
    }
    if (pass == 0) {
        if (t == 0 && src[0] < K) { st->fillmode = 1; st->T = 1u; st->b1 = -1; }
        __syncthreads();
        if (src[0] >= K) {
            for (int i = t; i < 2048; i += 256) {
                if (src[i] >= K && (i == 2047 || src[i + 1] < K)) {
                    st->b1 = i;
                    st->k2 = K - ((i == 2047) ? 0 : src[i + 1]);
                }
            }
        }
    } else {
        int b1 = st->b1;
        for (int i = t; i < 2048; i += 256) {
            if (src[i] >= K && (i == 2047 || src[i + 1] < K))
                st->T = ((unsigned)((b1 << 11) | i)) << 10;
        }
    }
}

__global__ void compact_kernel(const unsigned* __restrict__ keys,
                               unsigned* __restrict__ ck, int* __restrict__ ci) {
    int lvl = blockIdx.y;
    int N = c_NL[lvl];
    const unsigned* kk = keys + c_KB[lvl];
    unsigned* ckL = ck + lvl * CAP;
    int* ciL = ci + lvl * CAP;
    unsigned T = d_st[lvl].T;
    for (int i = blockIdx.x * blockDim.x + threadIdx.x; i < N; i += gridDim.x * blockDim.x) {
        unsigned k = kk[i];
        if (k && k >= T) {
            int p = atomicAdd(&d_st[lvl].cnt, 1);
            if (p < SCAP) { ckL[p] = k; ciL[p] = i; }
        }
    }
}

// grid (5), 1024 threads, 64KB dyn smem: descending bitonic over SCAP, tie = lowest index
__global__ void sort_kernel(const unsigned* __restrict__ ck, const int* __restrict__ ci,
                            float* __restrict__ slot_s, int* __restrict__ slot_i) {
    extern __shared__ ull s[];
    int lvl = blockIdx.x;
    const unsigned* ckL = ck + lvl * CAP;
    const int* ciL = ci + lvl * CAP;
    float* ss = slot_s + lvl * TOPKN;
    int* si = slot_i + lvl * TOPKN;
    int M = d_st[lvl].cnt; if (M > SCAP) M = SCAP;
    for (int i = threadIdx.x; i < SCAP; i += 1024)
        s[i] = (i < M) ? (((ull)ckL[i] << 32) | (unsigned)(~(unsigned)ciL[i])) : 0ull;
    __syncthreads();
    for (int k = 2; k <= SCAP; k <<= 1) {
        for (int j = k >> 1; j > 0; j >>= 1) {
            for (int i = threadIdx.x; i < SCAP; i += 1024) {
                int l2 = i ^ j;
                if (l2 > i) {
                    ull a = s[i], b = s[l2];
                    bool up = ((i & k) == 0);
                    if (up ? (a < b) : (a > b)) { s[i] = b; s[l2] = a; }
                }
            }
            __syncthreads();
        }
    }
    int outn = (M < TOPKN) ? M : TOPKN;
    for (int i = threadIdx.x; i < outn; i += 1024) {
        ull v = s[i];
        ss[i] = __uint_as_float((unsigned)(v >> 32));
        si[i] = (int)(~(unsigned)(v & 0xffffffffull));
    }
    if (threadIdx.x == 0) d_st[lvl].slotn = outn;
}

// grid (5), 1024 threads: fill remaining slots with first failing indices (ascending)
__global__ void fill_kernel(const unsigned* __restrict__ keys,
                            float* __restrict__ slot_s, int* __restrict__ slot_i) {
    __shared__ int scn[1024];
    __shared__ int s_coll;
    int lvl = blockIdx.x;
    int N = c_NL[lvl];
    const unsigned* kk = keys + c_KB[lvl];
    float* ss = slot_s + lvl * TOPKN;
    int* si = slot_i + lvl * TOPKN;
    int m = TOPKN - d_st[lvl].slotn;
    if (m <= 0) return;
    int base = d_st[lvl].slotn;
    if (threadIdx.x == 0) s_coll = 0;
    __syncthreads();
    for (int start = 0; start < N; start += 1024) {
        int collected = s_coll;
        if (collected >= m) break;
        int i = start + threadIdx.x;
        int fail = (i < N && kk[i] == 0u) ? 1 : 0;
        scn[threadIdx.x] = fail;
        __syncthreads();
        for (int d = 1; d < 1024; d <<= 1) {
            int v = scn[threadIdx.x];
            int add = (threadIdx.x >= (unsigned)d) ? scn[threadIdx.x - d] : 0;
            __syncthreads();
            scn[threadIdx.x] = v + add;
            __syncthreads();
        }
        int incl = scn[threadIdx.x];
        int excl = incl - fail;
        if (fail && collected + excl < m) {
            ss[base + collected + excl] = -1.0f;
            si[base + collected + excl] = i;
        }
        __syncthreads();
        if (threadIdx.x == 1023) s_coll = collected + incl;
        __syncthreads();
    }
}

// ------------- decode + clip + global box-max; grid (4,5) -------------
__global__ void decode_kernel(const float* __restrict__ REG, const float* __restrict__ anchors,
                              const float* __restrict__ slot_s, const int* __restrict__ slot_i,
                              float* __restrict__ cand_s, float* __restrict__ cand_b,
                              int* __restrict__ cand_l) {
    int lvl = blockIdx.y;
    int i = blockIdx.x * blockDim.x + threadIdx.x;
    if (i >= TOPKN) return;
    int HW = c_HW[lvl];
    int aOff = c_cumHW[lvl] * 9;
    const float* reg = REG + (size_t)c_cumHW[lvl] * 36;
    float sc = slot_s[lvl * TOPKN + i];
    int idx = slot_i[lvl * TOPKN + i];
    int c = idx % NCLS;
    int r = idx / NCLS;
    int a = r % NANC;
    int p = r / NANC;
    float r0 = reg[(size_t)(a * 4 + 0) * HW + p];
    float r1 = reg[(size_t)(a * 4 + 1) * HW + p];
    float r2 = reg[(size_t)(a * 4 + 2) * HW + p];
    float r3 = reg[(size_t)(a * 4 + 3) * HW + p];
    const float* an = anchors + (size_t)(aOff + r) * 4;
    float ax0 = an[0], ay0 = an[1], ax1 = an[2], ay1 = an[3];
    float w = ax1 - ax0, h = ay1 - ay0;
    float cx = ax0 + 0.5f * w, cy = ay0 + 0.5f * h;
    float dw = fminf(r2, BBOX_CLIP), dh = fminf(r3, BBOX_CLIP);
    float pcx = r0 * w + cx, pcy = r1 * h + cy;
    float pw = expf(dw) * w, ph = expf(dh) * h;
    float x0 = fminf(fmaxf(pcx - 0.5f * pw, 0.f), IMGSZ);
    float y0 = fminf(fmaxf(pcy - 0.5f * ph, 0.f), IMGSZ);
    float x1 = fminf(fmaxf(pcx + 0.5f * pw, 0.f), IMGSZ);
    float y1 = fminf(fmaxf(pcy + 0.5f * ph, 0.f), IMGSZ);
    int o = lvl * TOPKN + i;
    cand_s[o] = sc;
    cand_b[o * 4 + 0] = x0; cand_b[o * 4 + 1] = y0;
    cand_b[o * 4 + 2] = x1; cand_b[o * 4 + 3] = y1;
    cand_l[o] = c;
    float mx = fmaxf(fmaxf(x0, y0), fmaxf(x1, y1));
    atomicMax(&g_gmax, __float_as_int(mx));
}

// ------------- sequential NMS, 1024 threads, 5/thread, register-resident (no dyn idx) -------
__global__ void nms_kernel(const float* __restrict__ cs, const float* __restrict__ cb,
                           const int* __restrict__ cl, float* __restrict__ out, int out_size) {
    extern __shared__ float sm[];
    float* s0 = sm;
    float* s1 = sm + 5000;
    float* s2 = sm + 10000;
    float* s3 = sm + 15000;
    float* s4 = sm + 20000;
    __shared__ float rv[32];
    __shared__ int ri[32];
    __shared__ float sjv;
    __shared__ int sji;
    __shared__ int sel[DETSN];
    __shared__ int val[DETSN];
    int t = threadIdx.x;
    float off1 = __int_as_float(g_gmax) + 1.0f;
    float alive[5], b0[5], b1v[5], b2[5], b3[5], ar[5];
#pragma unroll
    for (int k = 0; k < 5; k++) {
        int e = t + k * 1024;
        if (e < 5000) {
            float s = cs[e];
            float o = (float)cl[e] * off1;
            float x0 = cb[e * 4 + 0] + o, y0 = cb[e * 4 + 1] + o;
            float x1 = cb[e * 4 + 2] + o, y1 = cb[e * 4 + 3] + o;
            b0[k] = x0; b1v[k] = y0; b2[k] = x1; b3[k] = y1;
            ar[k] = (x1 - x0) * (y1 - y0);
            s0[e] = x0; s1[e] = y0; s2[e] = x1; s3[e] = y1; s4[e] = ar[k];
            alive[k] = (s > 0.05f) ? s : NEGV;
        } else {
            alive[k] = -3.0e38f;
            b0[k] = b1v[k] = b2[k] = b3[k] = 0.f; ar[k] = 0.f;
        }
    }
    __syncthreads();
    for (int it = 0; it < DETSN; ++it) {
        float bv = -3.4e38f; int bi = 0x7fffffff;
#pragma unroll
        for (int k = 0; k < 5; k++) {
            int e = t + k * 1024;
            float v = alive[k];
            if (v > bv || (v == bv && e < bi)) { bv = v; bi = e; }
        }
        for (int o = 16; o > 0; o >>= 1) {
            float ov = __shfl_down_sync(0xffffffffu, bv, o);
            int oi = __shfl_down_sync(0xffffffffu, bi, o);
            if (ov > bv || (ov == bv && oi < bi)) { bv = ov; bi = oi; }
        }
        if ((t & 31) == 0) { rv[t >> 5] = bv; ri[t >> 5] = bi; }
        __syncthreads();
        if (t < 32) {
            bv = rv[t]; bi = ri[t];
            for (int o = 16; o > 0; o >>= 1) {
                float ov = __shfl_down_sync(0xffffffffu, bv, o);
                int oi = __shfl_down_sync(0xffffffffu, bi, o);
                if (ov > bv || (ov == bv && oi < bi)) { bv = ov; bi = oi; }
            }
            if (t == 0) { sjv = bv; sji = bi; }
        }
        __syncthreads();
        int j = sji; float vj = sjv;
        if (t == 0) { sel[it] = j; val[it] = (vj > 0.05f) ? 1 : 0; }
        float jx0 = s0[j], jy0 = s1[j], jx1 = s2[j], jy1 = s3[j], ja = s4[j];
#pragma unroll
        for (int k = 0; k < 5; k++) {
            int e = t + k * 1024;
            if (e == j) alive[k] = NEGV;
            float lt0 = fmaxf(jx0, b0[k]), lt1 = fmaxf(jy0, b1v[k]);
            float rb0 = fminf(jx1, b2[k]), rb1 = fminf(jy1, b3[k]);
            float w = fmaxf(rb0 - lt0, 0.f), h = fmaxf(rb1 - lt1, 0.f);
            float inter = w * h;
            float iou = inter / (ja + ar[k] - inter + 1e-12f);
            if (iou > 0.5f) alive[k] = NEGV;
        }
        __syncthreads();
    }
    for (int i = t; i < DETSN; i += 1024) {
        int j = sel[i]; int v = val[i];
        if (i * 5 + 4 < out_size) {
            out[i * 5 + 0] = v ? cs[j] : 0.f;
            out[i * 5 + 1] = v ? cb[j * 4 + 0] : 0.f;
            out[i * 5 + 2] = v ? cb[j * 4 + 1] : 0.f;
            out[i * 5 + 3] = v ? cb[j * 4 + 2] : 0.f;
            out[i * 5 + 4] = v ? cb[j * 4 + 3] : 0.f;
        }
        int li = DETSN * 5 + i;
        if (li < out_size) out[li] = v ? (float)cl[j] : -1.0f;
    }
    for (int i = DETSN * 6 + t; i < out_size; i += 1024) out[i] = 0.f;
}

extern "C" void kernel_launch(void* const* d_in, const int* in_sizes, int n_in,
                              void* d_out, int out_size) {
    const float* f0 = (const float*)d_in[0];
    const float* f1 = (const float*)d_in[1];
    const float* f2 = (const float*)d_in[2];
    const float* f3 = (const float*)d_in[3];
    const float* f4 = (const float*)d_in[4];
    const float* anchors = (const float*)d_in[5];
    const float* ctw = (const float*)d_in[6];
    const float* ctb = (const float*)d_in[7];
    const float* cow = (const float*)d_in[8];
    const float* cob = (const float*)d_in[9];
    const float* rtw = (const float*)d_in[10];
    const float* rtb = (const float*)d_in[11];
    const float* rbw = (const float*)d_in[12];
    const float* rbb = (const float*)d_in[13];

    float* S = nullptr;
    cudaGetSymbolAddress((void**)&S, g_scratch);
    cudaFuncSetAttribute(sort_kernel, cudaFuncAttributeMaxDynamicSharedMemorySize, SCAP * 8);
    cudaFuncSetAttribute(nms_kernel, cudaFuncAttributeMaxDynamicSharedMemorySize, 100000);

    float* WT_CT = S + OFF_WT_CT;
    float* WT_RT = S + OFF_WT_RT;
    float* WT_CL = S + OFF_WT_CL;
    float* WT_RB = S + OFF_WT_RB;
    float* BUFA = S + OFF_BUFA;
    float* BUFB = S + OFF_BUFB;
    float* BUFC = S + OFF_BUFC;
    float* BUFD = S + OFF_BUFD;
    float* LOG = S + OFF_LOG;
    float* REG = S + OFF_REG;
    unsigned* keys = (unsigned*)(S + OFF_KEYS);
    unsigned* ck = (unsigned*)(S + OFF_CK);
    int* ci = (int*)(S + OFF_CI);
    float* sls = S + OFF_SLS;
    int* sli = (int*)(S + OFF_SLI);
    float* cand_s = S + OFF_CS;
    float* cand_b = S + OFF_CB;
    int* cand_l = (int*)(S + OFF_CL2);

    const size_t TW = 589824;

    transpose_all<<<3072, 256>>>(ctw, rtw, cow, rbw);
    zero_all<<<40, 256>>>();

    dim3 gt(86, 16), gh(86, 28);
    conv_merged<<<gt, 128>>>(f0, f1, f2, f3, f4, nullptr, nullptr,
                             WT_CT + 0 * TW, ctb + 0, BUFA,
                             WT_RT + 0 * TW, rtb + 0, BUFC, 0, 0);
    conv_merged<<<gt, 128>>>(f0, f1, f2, f3, f4, BUFA, BUFC,
                             WT_CT + 1 * TW, ctb + 256, BUFB,
                             WT_RT + 1 * TW, rtb + 256, BUFD, 1, 0);
    conv_merged<<<gt, 128>>>(f0, f1, f2, f3, f4, BUFB, BUFD,
                             WT_CT + 2 * TW, ctb + 512, BUFA,
                             WT_RT + 2 * TW, rtb + 512, BUFC, 2, 0);
    conv_merged<<<gt, 128>>>(f0, f1, f2, f3, f4, BUFA, BUFC,
                             WT_CT + 3 * TW, ctb + 768, BUFB,
                             WT_RT + 3 * TW, rtb + 768, BUFD, 3, 0);
    conv_merged<<<gh, 128>>>(f0, f1, f2, f3, f4, BUFB, BUFD,
                             WT_CL, cob, LOG,
                             WT_RB, rbb, REG, 4, 1);

    keys_hist1_kernel<<<dim3(128, 5), 256>>>(LOG, keys);
    scan_kernel<<<5, 256>>>(0);
    hist2_kernel<<<dim3(64, 5), 256>>>(keys);
    scan_kernel<<<5, 256>>>(1);
    compact_kernel<<<dim3(64, 5), 256>>>(keys, ck, ci);
    sort_kernel<<<5, 1024, SCAP * 8>>>(ck, ci, sls, sli);
    fill_kernel<<<5, 1024>>>(keys, sls, sli);
    decode_kernel<<<dim3(4, 5), 256>>>(REG, anchors, sls, sli, cand_s, cand_b, cand_l);

    nms_kernel<<<1, 1024, 100000>>>(cand_s, cand_b, cand_l, (float*)d_out, out_size);
}

// round 16
// speedup vs baseline: 1.1960x; 1.1960x over previous
#include <cuda_runtime.h>
#include <math.h>

#define CIN 256
#define NCLS 91
#define NANC 9
#define TOPKN 1000
#define DETSN 300
#define CAP 16384
#define SCAP 8192
#define NEGV -1e9f
#define BBOX_CLIP 4.135166556742356f
#define IMGSZ 512.0f

typedef unsigned long long ull;

// ---------------- scratch layout (float units) ----------------
#define OFF_WT_CT 0ull
#define OFF_WT_RT 2359296ull
#define OFF_WT_CL 4718592ull
#define OFF_WT_RB 6782976ull
#define OFF_BUFA  7077888ull
#define OFF_BUFB  8474624ull
#define OFF_BUFC  9871360ull
#define OFF_BUFD  11268096ull
#define OFF_LOG   12664832ull
#define OFF_REG   17133296ull
#define OFF_KEYS  17329712ull
#define OFF_CK    21798176ull
#define OFF_CI    21880096ull
#define OFF_SLS   21962016ull
#define OFF_SLI   21967016ull
#define OFF_CS    21972016ull
#define OFF_CB    21977016ull
#define OFF_CL2   21997016ull
#define TOTAL_F   22002016ull

__device__ __align__(16) float g_scratch[TOTAL_F];

struct SelState {
    int cnt, slotn, fillmode, b1, k2;
    unsigned T;
    int hist1[2048];
    int hist2[2048];
};
__device__ SelState d_st[5];
__device__ int g_gmax;

// level constants
__constant__ int c_NL[5]    = {3354624, 838656, 209664, 52416, 13104};
__constant__ int c_KB[5]    = {0, 3354624, 4193280, 4402944, 4455360};
__constant__ int c_cumHW[5] = {0, 4096, 5120, 5376, 5440};
__constant__ int c_HW[5]    = {4096, 1024, 256, 64, 16};
__constant__ int c_logHW[5] = {12, 10, 8, 6, 4};

// ------------- packed f32x2 helpers -------------
__device__ __forceinline__ ull pk2(float lo, float hi) {
    ull r;
    asm("mov.b64 %0,{%1,%2};" : "=l"(r) : "f"(lo), "f"(hi));
    return r;
}
__device__ __forceinline__ void unpk2(ull v, float& lo, float& hi) {
    asm("mov.b64 {%0,%1},%2;" : "=f"(lo), "=f"(hi) : "l"(v));
}
__device__ __forceinline__ void ffma2(ull& d, ull a, ull b) {
    asm("fma.rn.f32x2 %0,%1,%2,%0;" : "+l"(d) : "l"(a), "l"(b));
}

// ------------- coalesced-write weight transpose: OIHW -> wT[k_lin][CoutPad] -------------
__global__ void transpose_all(const float* __restrict__ ctw, const float* __restrict__ rtw,
                              const float* __restrict__ cow, const float* __restrict__ rbw) {
    float* S = g_scratch;
    const int TN = 589824;
    long long g = (long long)blockIdx.x * blockDim.x + threadIdx.x;
    if (g < 262144) {
        int sub = (int)(g >> 16);
        int r = (int)(g & 65535);
        int ic = r >> 8, oc = r & 255;
        const float* src = ctw + (size_t)sub * TN + (size_t)oc * 2304 + ic * 9;
        float* dst = S + OFF_WT_CT + (size_t)sub * TN + (size_t)ic * 256 + oc;
#pragma unroll
        for (int tap = 0; tap < 9; tap++) dst[(size_t)tap * 65536] = src[tap];
    } else if (g < 524288) {
        g -= 262144;
        int sub = (int)(g >> 16);
        int r = (int)(g & 65535);
        int ic = r >> 8, oc = r & 255;
        const float* src = rtw + (size_t)sub * TN + (size_t)oc * 2304 + ic * 9;
        float* dst = S + OFF_WT_RT + (size_t)sub * TN + (size_t)ic * 256 + oc;
#pragma unroll
        for (int tap = 0; tap < 9; tap++) dst[(size_t)tap * 65536] = src[tap];
    } else if (g < 753664) {
        int r = (int)(g - 524288);
        int ic = r / 896, oc = r % 896;
        float* dst = S + OFF_WT_CL + (size_t)ic * 896 + oc;
        if (oc < 819) {
            const float* src = cow + (size_t)oc * 2304 + ic * 9;
#pragma unroll
            for (int tap = 0; tap < 9; tap++) dst[(size_t)tap * 229376] = src[tap];
        } else {
#pragma unroll
            for (int tap = 0; tap < 9; tap++) dst[(size_t)tap * 229376] = 0.f;
        }
    } else if (g < 786432) {
        int r = (int)(g - 753664);
        int ic = r >> 7, oc = r & 127;
        float* dst = S + OFF_WT_RB + (size_t)ic * 128 + oc;
        if (oc < 36) {
            const float* src = rbw + (size_t)oc * 2304 + ic * 9;
#pragma unroll
            for (int tap = 0; tap < 9; tap++) dst[(size_t)tap * 32768] = src[tap];
        } else {
#pragma unroll
            for (int tap = 0; tap < 9; tap++) dst[(size_t)tap * 32768] = 0.f;
        }
    }
}

// ------------- zero all selection state -------------
__global__ void zero_all() {
    int t = blockIdx.x * blockDim.x + threadIdx.x;
    if (t < 5 * 2048) {
        int l = t / 2048, e = t % 2048;
        d_st[l].hist1[e] = 0;
        d_st[l].hist2[e] = 0;
    }
    if (t < 5) {
        d_st[t].cnt = 0; d_st[t].slotn = 0; d_st[t].fillmode = 0;
        d_st[t].b1 = -1; d_st[t].k2 = 0; d_st[t].T = 0u;
    }
    if (t == 5) g_gmax = 0;
}

// ------------- merged 3x3 SAME conv (R14 design): 64oc x 64px tile, 128 threads,
//               8oc x 4px microtile, incremental tap-cached fetch; 6 CTAs/SM target -------------
__global__ void __launch_bounds__(128, 6) conv_merged(
    const float* __restrict__ f0, const float* __restrict__ f1, const float* __restrict__ f2,
    const float* __restrict__ f3, const float* __restrict__ f4,
    const float* __restrict__ cinBuf, const float* __restrict__ rinBuf,
    const float* __restrict__ wTc, const float* __restrict__ bc, float* __restrict__ coutBuf,
    const float* __restrict__ wTr, const float* __restrict__ br, float* __restrict__ routBuf,
    int stage, int head) {
    __shared__ float As[2][16][64];
    __shared__ float Bs[2][16][64];

    int bx = blockIdx.x;
    int l, gxB;
    if (bx < 64)      { l = 0; gxB = 0; }
    else if (bx < 80) { l = 1; gxB = 64; }
    else if (bx < 84) { l = 2; gxB = 80; }
    else if (bx < 85) { l = 3; gxB = 84; }
    else              { l = 4; gxB = 85; }
    int logW = 6 - l;
    int W = 1 << logW, HW = W * W;
    int cum = c_cumHW[l];
    int pxBase = (bx - gxB) * 64;

    const float* in; const float* wT; const float* bias; float* out;
    int Cout, CoutPad, ocBase, relu;
    int y = blockIdx.y;
    if (!head) {
        relu = 1; Cout = 256; CoutPad = 256;
        ocBase = (y & 3) * 64;
        if ((y >> 2) == 0) {
            wT = wTc; bias = bc; out = coutBuf + (size_t)cum * 256;
            in = cinBuf + (size_t)cum * 256;
        } else {
            wT = wTr; bias = br; out = routBuf + (size_t)cum * 256;
            in = rinBuf + (size_t)cum * 256;
        }
        if (stage == 0)
            in = (l == 0) ? f0 : (l == 1) ? f1 : (l == 2) ? f2 : (l == 3) ? f3 : f4;
    } else {
        relu = 0;
        if (y < 13) {
            ocBase = y * 64; Cout = 819; CoutPad = 896;
            wT = wTc; bias = bc;
            in = cinBuf + (size_t)cum * 256;
            out = coutBuf + (size_t)cum * 819;
        } else {
            ocBase = 0; Cout = 36; CoutPad = 128;
            wT = wTr; bias = br;
            in = rinBuf + (size_t)cum * 256;
            out = routBuf + (size_t)cum * 36;
        }
    }

    int tid = threadIdx.x;
    int tx = tid & 15, ty = tid >> 4;

    int pxF = tid & 63;
    int kB0 = tid >> 6;
    int pF = pxBase + pxF;
    int prow = pF >> logW;
    int pcol = pF & (W - 1);
    bool okp = pF < HW;

    ull acc[8][2];
#pragma unroll
    for (int i = 0; i < 8; i++) { acc[i][0] = 0ull; acc[i][1] = 0ull; }

    float4 pa0, pa1;
    float pb[8];

    int tapCur = -1;
    bool okT = false;
    long bcur = 0;
    const float* wptr = wT + (size_t)(tid >> 4) * CoutPad + ocBase + ((tid & 15) << 2);
    const size_t wInc = (size_t)16 * CoutPad;
    const size_t w8 = (size_t)8 * CoutPad;
    const long bInc = (long)16 * HW;

    auto fetch = [&](int c) {
        int tap = c >> 4;
        if (tap != tapCur) {
            tapCur = tap;
            int dy = tap / 3 - 1, dx = tap % 3 - 1;
            int hh = prow + dy, ww = pcol + dx;
            okT = okp && ((unsigned)hh < (unsigned)W) && ((unsigned)ww < (unsigned)W);
            bcur = (long)kB0 * HW + (((long)hh) << logW) + ww;
        }
#pragma unroll
        for (int i = 0; i < 8; i++)
            pb[i] = okT ? in[bcur + (long)2 * i * HW] : 0.f;
        bcur += bInc;
        pa0 = *(const float4*)(wptr);
        pa1 = *(const float4*)(wptr + w8);
        wptr += wInc;
    };
    auto stor = [&](int buf) {
        float4* asf = (float4*)&As[buf][0][0];
        asf[tid] = pa0;
        asf[128 + tid] = pa1;
#pragma unroll
        for (int i = 0; i < 8; i++) Bs[buf][kB0 + 2 * i][pxF] = pb[i];
    };

    fetch(0);
    stor(0);
    __syncthreads();

    const int NC = 144;
    for (int c = 0; c < NC; c++) {
        int buf = c & 1;
        if (c + 1 < NC) fetch(c + 1);
#pragma unroll
        for (int k = 0; k < 16; k++) {
            float4 a0 = *(const float4*)&As[buf][k][ty << 3];
            float4 a1 = *(const float4*)&As[buf][k][(ty << 3) + 4];
            ulonglong2 b01 = *(const ulonglong2*)&Bs[buf][k][tx << 2];
            float av[8] = {a0.x, a0.y, a0.z, a0.w, a1.x, a1.y, a1.z, a1.w};
#pragma unroll
            for (int i = 0; i < 8; i++) {
                ull aa = pk2(av[i], av[i]);
                ffma2(acc[i][0], aa, b01.x);
                ffma2(acc[i][1], aa, b01.y);
            }
        }
        if (c + 1 < NC) stor(buf ^ 1);
        __syncthreads();
    }

#pragma unroll
    for (int i = 0; i < 8; i++) {
        int oc = ocBase + (ty << 3) + i;
        if (oc >= Cout) continue;
        float bvl = bias[oc];
        size_t ob = (size_t)oc * HW;
#pragma unroll
        for (int j = 0; j < 2; j++) {
            float lo, hi;
            unpk2(acc[i][j], lo, hi);
            int px = pxBase + (tx << 2) + 2 * j;
            if (px < HW) {
                float v = lo + bvl;
                if (relu) v = fmaxf(v, 0.f);
                out[ob + px] = v;
            }
            if (px + 1 < HW) {
                float v = hi + bvl;
                if (relu) v = fmaxf(v, 0.f);
                out[ob + px + 1] = v;
            }
        }
    }
}

// ------------- fused sigmoid keys + hist1 (memory-order); grid (128, 5) -------------
__global__ void keys_hist1_kernel(const float* __restrict__ LOG, unsigned* __restrict__ keys) {
    __shared__ int h[2048];
    int lvl = blockIdx.y;
    int HW = c_HW[lvl];
    int logHW = c_logHW[lvl];
    int total = 819 << logHW;
    const float* lg0 = LOG + (size_t)c_cumHW[lvl] * 819;
    unsigned* kk = keys + c_KB[lvl];
    for (int i = threadIdx.x; i < 2048; i += blockDim.x) h[i] = 0;
    __syncthreads();
    int stride = gridDim.x * blockDim.x;
    for (int idx = blockIdx.x * blockDim.x + threadIdx.x; idx < total; idx += stride) {
        int ch = idx >> logHW;
        int p = idx & (HW - 1);
        float lg = lg0[idx];
        float s = 1.f / (1.f + expf(-lg));
        unsigned k = (s > 0.05f) ? __float_as_uint(s) : 0u;
        kk[(size_t)p * 819 + ch] = k;
        if (k) atomicAdd(&h[k >> 21], 1);
    }
    __syncthreads();
    for (int i = threadIdx.x; i < 2048; i += blockDim.x)
        if (h[i]) atomicAdd(&d_st[lvl].hist1[i], h[i]);
}

__global__ void hist2_kernel(const unsigned* __restrict__ keys) {
    __shared__ int h[2048];
    int lvl = blockIdx.y;
    int b1 = d_st[lvl].b1;
    if (b1 < 0) return;
    int N = c_NL[lvl];
    const unsigned* kk = keys + c_KB[lvl];
    for (int i = threadIdx.x; i < 2048; i += blockDim.x) h[i] = 0;
    __syncthreads();
    for (int i = blockIdx.x * blockDim.x + threadIdx.x; i < N; i += gridDim.x * blockDim.x) {
        unsigned k = kk[i];
        if (k && (int)(k >> 21) == b1) atomicAdd(&h[(k >> 10) & 2047], 1);
    }
    __syncthreads();
    for (int i = threadIdx.x; i < 2048; i += blockDim.x)
        if (h[i]) atomicAdd(&d_st[lvl].hist2[i], h[i]);
}

// grid (5), 256 threads
__global__ void scan_kernel(int pass) {
    __shared__ int s0[2048], s1[2048];
    SelState* st = &d_st[blockIdx.x];
    if (pass == 1 && st->fillmode) return;
    int* hist = (pass == 0) ? st->hist1 : st->hist2;
    int K = (pass == 0) ? TOPKN : st->k2;
    int t = threadIdx.x;
    for (int i = t; i < 2048; i += 256) s0[i] = hist[i];
    __syncthreads();
    int* src = s0; int* dst = s1;
    for (int d = 1; d < 2048; d <<= 1) {
        for (int i = t; i < 2048; i += 256)
            dst[i] = src[i] + ((i + d < 2048) ? src[i + d] : 0);
        __syncthreads();
        int* tmp = src; src = dst; dst = tmp;
    }
    if (pass == 0) {
        if (t == 0 && src[0] < K) { st->fillmode = 1; st->T = 1u; st->b1 = -1; }
        __syncthreads();
        if (src[0] >= K) {
            for (int i = t; i < 2048; i += 256) {
                if (src[i] >= K && (i == 2047 || src[i + 1] < K)) {
                    st->b1 = i;
                    st->k2 = K - ((i == 2047) ? 0 : src[i + 1]);
                }
            }
        }
    } else {
        int b1 = st->b1;
        for (int i = t; i < 2048; i += 256) {
            if (src[i] >= K && (i == 2047 || src[i + 1] < K))
                st->T = ((unsigned)((b1 << 11) | i)) << 10;
        }
    }
}

__global__ void compact_kernel(const unsigned* __restrict__ keys,
                               unsigned* __restrict__ ck, int* __restrict__ ci) {
    int lvl = blockIdx.y;
    int N = c_NL[lvl];
    const unsigned* kk = keys + c_KB[lvl];
    unsigned* ckL = ck + lvl * CAP;
    int* ciL = ci + lvl * CAP;
    unsigned T = d_st[lvl].T;
    for (int i = blockIdx.x * blockDim.x + threadIdx.x; i < N; i += gridDim.x * blockDim.x) {
        unsigned k = kk[i];
        if (k && k >= T) {
            int p = atomicAdd(&d_st[lvl].cnt, 1);
            if (p < SCAP) { ckL[p] = k; ciL[p] = i; }
        }
    }
}

// grid (5), 1024 threads, 64KB dyn smem: descending bitonic over SCAP, tie = lowest index
__global__ void sort_kernel(const unsigned* __restrict__ ck, const int* __restrict__ ci,
                            float* __restrict__ slot_s, int* __restrict__ slot_i) {
    extern __shared__ ull s[];
    int lvl = blockIdx.x;
    const unsigned* ckL = ck + lvl * CAP;
    const int* ciL = ci + lvl * CAP;
    float* ss = slot_s + lvl * TOPKN;
    int* si = slot_i + lvl * TOPKN;
    int M = d_st[lvl].cnt; if (M > SCAP) M = SCAP;
    for (int i = threadIdx.x; i < SCAP; i += 1024)
        s[i] = (i < M) ? (((ull)ckL[i] << 32) | (unsigned)(~(unsigned)ciL[i])) : 0ull;
    __syncthreads();
    for (int k = 2; k <= SCAP; k <<= 1) {
        for (int j = k >> 1; j > 0; j >>= 1) {
            for (int i = threadIdx.x; i < SCAP; i += 1024) {
                int l2 = i ^ j;
                if (l2 > i) {
                    ull a = s[i], b = s[l2];
                    bool up = ((i & k) == 0);
                    if (up ? (a < b) : (a > b)) { s[i] = b; s[l2] = a; }
                }
            }
            __syncthreads();
        }
    }
    int outn = (M < TOPKN) ? M : TOPKN;
    for (int i = threadIdx.x; i < outn; i += 1024) {
        ull v = s[i];
        ss[i] = __uint_as_float((unsigned)(v >> 32));
        si[i] = (int)(~(unsigned)(v & 0xffffffffull));
    }
    if (threadIdx.x == 0) d_st[lvl].slotn = outn;
}

// grid (5), 1024 threads: fill remaining slots with first failing indices (ascending)
__global__ void fill_kernel(const unsigned* __restrict__ keys,
                            float* __restrict__ slot_s, int* __restrict__ slot_i) {
    __shared__ int scn[1024];
    __shared__ int s_coll;
    int lvl = blockIdx.x;
    int N = c_NL[lvl];
    const unsigned* kk = keys + c_KB[lvl];
    float* ss = slot_s + lvl * TOPKN;
    int* si = slot_i + lvl * TOPKN;
    int m = TOPKN - d_st[lvl].slotn;
    if (m <= 0) return;
    int base = d_st[lvl].slotn;
    if (threadIdx.x == 0) s_coll = 0;
    __syncthreads();
    for (int start = 0; start < N; start += 1024) {
        int collected = s_coll;
        if (collected >= m) break;
        int i = start + threadIdx.x;
        int fail = (i < N && kk[i] == 0u) ? 1 : 0;
        scn[threadIdx.x] = fail;
        __syncthreads();
        for (int d = 1; d < 1024; d <<= 1) {
            int v = scn[threadIdx.x];
            int add = (threadIdx.x >= (unsigned)d) ? scn[threadIdx.x - d] : 0;
            __syncthreads();
            scn[threadIdx.x] = v + add;
            __syncthreads();
        }
        int incl = scn[threadIdx.x];
        int excl = incl - fail;
        if (fail && collected + excl < m) {
            ss[base + collected + excl] = -1.0f;
            si[base + collected + excl] = i;
        }
        __syncthreads();
        if (threadIdx.x == 1023) s_coll = collected + incl;
        __syncthreads();
    }
}

// ------------- decode + clip + global box-max; grid (4,5) -------------
__global__ void decode_kernel(const float* __restrict__ REG, const float* __restrict__ anchors,
                              const float* __restrict__ slot_s, const int* __restrict__ slot_i,
                              float* __restrict__ cand_s, float* __restrict__ cand_b,
                              int* __restrict__ cand_l) {
    int lvl = blockIdx.y;
    int i = blockIdx.x * blockDim.x + threadIdx.x;
    if (i >= TOPKN) return;
    int HW = c_HW[lvl];
    int aOff = c_cumHW[lvl] * 9;
    const float* reg = REG + (size_t)c_cumHW[lvl] * 36;
    float sc = slot_s[lvl * TOPKN + i];
    int idx = slot_i[lvl * TOPKN + i];
    int c = idx % NCLS;
    int r = idx / NCLS;
    int a = r % NANC;
    int p = r / NANC;
    float r0 = reg[(size_t)(a * 4 + 0) * HW + p];
    float r1 = reg[(size_t)(a * 4 + 1) * HW + p];
    float r2 = reg[(size_t)(a * 4 + 2) * HW + p];
    float r3 = reg[(size_t)(a * 4 + 3) * HW + p];
    const float* an = anchors + (size_t)(aOff + r) * 4;
    float ax0 = an[0], ay0 = an[1], ax1 = an[2], ay1 = an[3];
    float w = ax1 - ax0, h = ay1 - ay0;
    float cx = ax0 + 0.5f * w, cy = ay0 + 0.5f * h;
    float dw = fminf(r2, BBOX_CLIP), dh = fminf(r3, BBOX_CLIP);
    float pcx = r0 * w + cx, pcy = r1 * h + cy;
    float pw = expf(dw) * w, ph = expf(dh) * h;
    float x0 = fminf(fmaxf(pcx - 0.5f * pw, 0.f), IMGSZ);
    float y0 = fminf(fmaxf(pcy - 0.5f * ph, 0.f), IMGSZ);
    float x1 = fminf(fmaxf(pcx + 0.5f * pw, 0.f), IMGSZ);
    float y1 = fminf(fmaxf(pcy + 0.5f * ph, 0.f), IMGSZ);
    int o = lvl * TOPKN + i;
    cand_s[o] = sc;
    cand_b[o * 4 + 0] = x0; cand_b[o * 4 + 1] = y0;
    cand_b[o * 4 + 2] = x1; cand_b[o * 4 + 3] = y1;
    cand_l[o] = c;
    float mx = fmaxf(fmaxf(x0, y0), fmaxf(x1, y1));
    atomicMax(&g_gmax, __float_as_int(mx));
}

// ------------- sequential NMS, 1024 threads, 5/thread, register-resident (no dyn idx) -------
__global__ void nms_kernel(const float* __restrict__ cs, const float* __restrict__ cb,
                           const int* __restrict__ cl, float* __restrict__ out, int out_size) {
    extern __shared__ float sm[];
    float* s0 = sm;
    float* s1 = sm + 5000;
    float* s2 = sm + 10000;
    float* s3 = sm + 15000;
    float* s4 = sm + 20000;
    __shared__ float rv[32];
    __shared__ int ri[32];
    __shared__ float sjv;
    __shared__ int sji;
    __shared__ int sel[DETSN];
    __shared__ int val[DETSN];
    int t = threadIdx.x;
    float off1 = __int_as_float(g_gmax) + 1.0f;
    float alive[5], b0[5], b1v[5], b2[5], b3[5], ar[5];
#pragma unroll
    for (int k = 0; k < 5; k++) {
        int e = t + k * 1024;
        if (e < 5000) {
            float s = cs[e];
            float o = (float)cl[e] * off1;
            float x0 = cb[e * 4 + 0] + o, y0 = cb[e * 4 + 1] + o;
            float x1 = cb[e * 4 + 2] + o, y1 = cb[e * 4 + 3] + o;
            b0[k] = x0; b1v[k] = y0; b2[k] = x1; b3[k] = y1;
            ar[k] = (x1 - x0) * (y1 - y0);
            s0[e] = x0; s1[e] = y0; s2[e] = x1; s3[e] = y1; s4[e] = ar[k];
            alive[k] = (s > 0.05f) ? s : NEGV;
        } else {
            alive[k] = -3.0e38f;
            b0[k] = b1v[k] = b2[k] = b3[k] = 0.f; ar[k] = 0.f;
        }
    }
    __syncthreads();
    for (int it = 0; it < DETSN; ++it) {
        float bv = -3.4e38f; int bi = 0x7fffffff;
#pragma unroll
        for (int k = 0; k < 5; k++) {
            int e = t + k * 1024;
            float v = alive[k];
            if (v > bv || (v == bv && e < bi)) { bv = v; bi = e; }
        }
        for (int o = 16; o > 0; o >>= 1) {
            float ov = __shfl_down_sync(0xffffffffu, bv, o);
            int oi = __shfl_down_sync(0xffffffffu, bi, o);
            if (ov > bv || (ov == bv && oi < bi)) { bv = ov; bi = oi; }
        }
        if ((t & 31) == 0) { rv[t >> 5] = bv; ri[t >> 5] = bi; }
        __syncthreads();
        if (t < 32) {
            bv = rv[t]; bi = ri[t];
            for (int o = 16; o > 0; o >>= 1) {
                float ov = __shfl_down_sync(0xffffffffu, bv, o);
                int oi = __shfl_down_sync(0xffffffffu, bi, o);
                if (ov > bv || (ov == bv && oi < bi)) { bv = ov; bi = oi; }
            }
            if (t == 0) { sjv = bv; sji = bi; }
        }
        __syncthreads();
        int j = sji; float vj = sjv;
        if (t == 0) { sel[it] = j; val[it] = (vj > 0.05f) ? 1 : 0; }
        float jx0 = s0[j], jy0 = s1[j], jx1 = s2[j], jy1 = s3[j], ja = s4[j];
#pragma unroll
        for (int k = 0; k < 5; k++) {
            int e = t + k * 1024;
            if (e == j) alive[k] = NEGV;
            float lt0 = fmaxf(jx0, b0[k]), lt1 = fmaxf(jy0, b1v[k]);
            float rb0 = fminf(jx1, b2[k]), rb1 = fminf(jy1, b3[k]);
            float w = fmaxf(rb0 - lt0, 0.f), h = fmaxf(rb1 - lt1, 0.f);
            float inter = w * h;
            float iou = inter / (ja + ar[k] - inter + 1e-12f);
            if (iou > 0.5f) alive[k] = NEGV;
        }
        __syncthreads();
    }
    for (int i = t; i < DETSN; i += 1024) {
        int j = sel[i]; int v = val[i];
        if (i * 5 + 4 < out_size) {
            out[i * 5 + 0] = v ? cs[j] : 0.f;
            out[i * 5 + 1] = v ? cb[j * 4 + 0] : 0.f;
            out[i * 5 + 2] = v ? cb[j * 4 + 1] : 0.f;
            out[i * 5 + 3] = v ? cb[j * 4 + 2] : 0.f;
            out[i * 5 + 4] = v ? cb[j * 4 + 3] : 0.f;
        }
        int li = DETSN * 5 + i;
        if (li < out_size) out[li] = v ? (float)cl[j] : -1.0f;
    }
    for (int i = DETSN * 6 + t; i < out_size; i += 1024) out[i] = 0.f;
}

extern "C" void kernel_launch(void* const* d_in, const int* in_sizes, int n_in,
                              void* d_out, int out_size) {
    const float* f0 = (const float*)d_in[0];
    const float* f1 = (const float*)d_in[1];
    const float* f2 = (const float*)d_in[2];
    const float* f3 = (const float*)d_in[3];
    const float* f4 = (const float*)d_in[4];
    const float* anchors = (const float*)d_in[5];
    const float* ctw = (const float*)d_in[6];
    const float* ctb = (const float*)d_in[7];
    const float* cow = (const float*)d_in[8];
    const float* cob = (const float*)d_in[9];
    const float* rtw = (const float*)d_in[10];
    const float* rtb = (const float*)d_in[11];
    const float* rbw = (const float*)d_in[12];
    const float* rbb = (const float*)d_in[13];

    float* S = nullptr;
    cudaGetSymbolAddress((void**)&S, g_scratch);
    cudaFuncSetAttribute(sort_kernel, cudaFuncAttributeMaxDynamicSharedMemorySize, SCAP * 8);
    cudaFuncSetAttribute(nms_kernel, cudaFuncAttributeMaxDynamicSharedMemorySize, 100000);

    float* WT_CT = S + OFF_WT_CT;
    float* WT_RT = S + OFF_WT_RT;
    float* WT_CL = S + OFF_WT_CL;
    float* WT_RB = S + OFF_WT_RB;
    float* BUFA = S + OFF_BUFA;
    float* BUFB = S + OFF_BUFB;
    float* BUFC = S + OFF_BUFC;
    float* BUFD = S + OFF_BUFD;
    float* LOG = S + OFF_LOG;
    float* REG = S + OFF_REG;
    unsigned* keys = (unsigned*)(S + OFF_KEYS);
    unsigned* ck = (unsigned*)(S + OFF_CK);
    int* ci = (int*)(S + OFF_CI);
    float* sls = S + OFF_SLS;
    int* sli = (int*)(S + OFF_SLI);
    float* cand_s = S + OFF_CS;
    float* cand_b = S + OFF_CB;
    int* cand_l = (int*)(S + OFF_CL2);

    const size_t TW = 589824;

    transpose_all<<<3072, 256>>>(ctw, rtw, cow, rbw);
    zero_all<<<40, 256>>>();

    dim3 gt(86, 8), gh(86, 14);
    conv_merged<<<gt, 128>>>(f0, f1, f2, f3, f4, nullptr, nullptr,
                             WT_CT + 0 * TW, ctb + 0, BUFA,
                             WT_RT + 0 * TW, rtb + 0, BUFC, 0, 0);
    conv_merged<<<gt, 128>>>(f0, f1, f2, f3, f4, BUFA, BUFC,
                             WT_CT + 1 * TW, ctb + 256, BUFB,
                             WT_RT + 1 * TW, rtb + 256, BUFD, 1, 0);
    conv_merged<<<gt, 128>>>(f0, f1, f2, f3, f4, BUFB, BUFD,
                             WT_CT + 2 * TW, ctb + 512, BUFA,
                             WT_RT + 2 * TW, rtb + 512, BUFC, 2, 0);
    conv_merged<<<gt, 128>>>(f0, f1, f2, f3, f4, BUFA, BUFC,
                             WT_CT + 3 * TW, ctb + 768, BUFB,
                             WT_RT + 3 * TW, rtb + 768, BUFD, 3, 0);
    conv_merged<<<gh, 128>>>(f0, f1, f2, f3, f4, BUFB, BUFD,
                             WT_CL, cob, LOG,
                             WT_RB, rbb, REG, 4, 1);

    keys_hist1_kernel<<<dim3(128, 5), 256>>>(LOG, keys);
    scan_kernel<<<5, 256>>>(0);
    hist2_kernel<<<dim3(64, 5), 256>>>(keys);
    scan_kernel<<<5, 256>>>(1);
    compact_kernel<<<dim3(64, 5), 256>>>(keys, ck, ci);
    sort_kernel<<<5, 1024, SCAP * 8>>>(ck, ci, sls, sli);
    fill_kernel<<<5, 1024>>>(keys, sls, sli);
    decode_kernel<<<dim3(4, 5), 256>>>(REG, anchors, sls, sli, cand_s, cand_b, cand_l);

    nms_kernel<<<1, 1024, 100000>>>(cand_s, cand_b, cand_l, (float*)d_out, out_size);
}

// round 17
// speedup vs baseline: 1.2701x; 1.0619x over previous
#include <cuda_runtime.h>
#include <math.h>

#define CIN 256
#define NCLS 91
#define NANC 9
#define TOPKN 1000
#define DETSN 300
#define CAP 16384
#define SCAP 8192
#define NEGV -1e9f
#define BBOX_CLIP 4.135166556742356f
#define IMGSZ 512.0f
#define LOGIT_PREF -2.9544f

typedef unsigned long long ull;

// ---------------- scratch layout (float units) ----------------
#define OFF_WT_CT 0ull
#define OFF_WT_RT 2359296ull
#define OFF_WT_CL 4718592ull
#define OFF_WT_RB 6782976ull
#define OFF_BUFA  7077888ull
#define OFF_BUFB  8474624ull
#define OFF_BUFC  9871360ull
#define OFF_BUFD  11268096ull
#define OFF_LOG   12664832ull
#define OFF_REG   17133296ull
#define OFF_KEYS  17329712ull
#define OFF_CK    21798176ull
#define OFF_CI    21880096ull
#define OFF_SLS   21962016ull
#define OFF_SLI   21967016ull
#define OFF_CS    21972016ull
#define OFF_CB    21977016ull
#define OFF_CL2   21997016ull
#define TOTAL_F   22002016ull

__device__ __align__(16) float g_scratch[TOTAL_F];

struct SelState {
    int cnt, slotn;
};
__device__ SelState d_st[5];
__device__ int g_gmax;

// level constants
__constant__ int c_NL[5]    = {3354624, 838656, 209664, 52416, 13104};
__constant__ int c_KB[5]    = {0, 3354624, 4193280, 4402944, 4455360};
__constant__ int c_cumHW[5] = {0, 4096, 5120, 5376, 5440};
__constant__ int c_HW[5]    = {4096, 1024, 256, 64, 16};
__constant__ int c_logHW[5] = {12, 10, 8, 6, 4};

// ------------- packed f32x2 helpers -------------
__device__ __forceinline__ ull pk2(float lo, float hi) {
    ull r;
    asm("mov.b64 %0,{%1,%2};" : "=l"(r) : "f"(lo), "f"(hi));
    return r;
}
__device__ __forceinline__ void unpk2(ull v, float& lo, float& hi) {
    asm("mov.b64 {%0,%1},%2;" : "=f"(lo), "=f"(hi) : "l"(v));
}
__device__ __forceinline__ void ffma2(ull& d, ull a, ull b) {
    asm("fma.rn.f32x2 %0,%1,%2,%0;" : "+l"(d) : "l"(a), "l"(b));
}

// ------------- coalesced-write weight transpose: OIHW -> wT[k_lin][CoutPad] -------------
__global__ void transpose_all(const float* __restrict__ ctw, const float* __restrict__ rtw,
                              const float* __restrict__ cow, const float* __restrict__ rbw) {
    float* S = g_scratch;
    const int TN = 589824;
    long long g = (long long)blockIdx.x * blockDim.x + threadIdx.x;
    if (g < 262144) {
        int sub = (int)(g >> 16);
        int r = (int)(g & 65535);
        int ic = r >> 8, oc = r & 255;
        const float* src = ctw + (size_t)sub * TN + (size_t)oc * 2304 + ic * 9;
        float* dst = S + OFF_WT_CT + (size_t)sub * TN + (size_t)ic * 256 + oc;
#pragma unroll
        for (int tap = 0; tap < 9; tap++) dst[(size_t)tap * 65536] = src[tap];
    } else if (g < 524288) {
        g -= 262144;
        int sub = (int)(g >> 16);
        int r = (int)(g & 65535);
        int ic = r >> 8, oc = r & 255;
        const float* src = rtw + (size_t)sub * TN + (size_t)oc * 2304 + ic * 9;
        float* dst = S + OFF_WT_RT + (size_t)sub * TN + (size_t)ic * 256 + oc;
#pragma unroll
        for (int tap = 0; tap < 9; tap++) dst[(size_t)tap * 65536] = src[tap];
    } else if (g < 753664) {
        int r = (int)(g - 524288);
        int ic = r / 896, oc = r % 896;
        float* dst = S + OFF_WT_CL + (size_t)ic * 896 + oc;
        if (oc < 819) {
            const float* src = cow + (size_t)oc * 2304 + ic * 9;
#pragma unroll
            for (int tap = 0; tap < 9; tap++) dst[(size_t)tap * 229376] = src[tap];
        } else {
#pragma unroll
            for (int tap = 0; tap < 9; tap++) dst[(size_t)tap * 229376] = 0.f;
        }
    } else if (g < 786432) {
        int r = (int)(g - 753664);
        int ic = r >> 7, oc = r & 127;
        float* dst = S + OFF_WT_RB + (size_t)ic * 128 + oc;
        if (oc < 36) {
            const float* src = rbw + (size_t)oc * 2304 + ic * 9;
#pragma unroll
            for (int tap = 0; tap < 9; tap++) dst[(size_t)tap * 32768] = src[tap];
        } else {
#pragma unroll
            for (int tap = 0; tap < 9; tap++) dst[(size_t)tap * 32768] = 0.f;
        }
    }
}

// ------------- zero selection state -------------
__global__ void zero_all() {
    int t = blockIdx.x * blockDim.x + threadIdx.x;
    if (t < 5) { d_st[t].cnt = 0; d_st[t].slotn = 0; }
    if (t == 5) g_gmax = 0;
}

// ------------- merged 3x3 SAME conv (R14/R16 design): 64oc x 64px tile, 128 threads -------------
__global__ void __launch_bounds__(128, 6) conv_merged(
    const float* __restrict__ f0, const float* __restrict__ f1, const float* __restrict__ f2,
    const float* __restrict__ f3, const float* __restrict__ f4,
    const float* __restrict__ cinBuf, const float* __restrict__ rinBuf,
    const float* __restrict__ wTc, const float* __restrict__ bc, float* __restrict__ coutBuf,
    const float* __restrict__ wTr, const float* __restrict__ br, float* __restrict__ routBuf,
    int stage, int head) {
    __shared__ float As[2][16][64];
    __shared__ float Bs[2][16][64];

    int bx = blockIdx.x;
    int l, gxB;
    if (bx < 64)      { l = 0; gxB = 0; }
    else if (bx < 80) { l = 1; gxB = 64; }
    else if (bx < 84) { l = 2; gxB = 80; }
    else if (bx < 85) { l = 3; gxB = 84; }
    else              { l = 4; gxB = 85; }
    int logW = 6 - l;
    int W = 1 << logW, HW = W * W;
    int cum = c_cumHW[l];
    int pxBase = (bx - gxB) * 64;

    const float* in; const float* wT; const float* bias; float* out;
    int Cout, CoutPad, ocBase, relu;
    int y = blockIdx.y;
    if (!head) {
        relu = 1; Cout = 256; CoutPad = 256;
        ocBase = (y & 3) * 64;
        if ((y >> 2) == 0) {
            wT = wTc; bias = bc; out = coutBuf + (size_t)cum * 256;
            in = cinBuf + (size_t)cum * 256;
        } else {
            wT = wTr; bias = br; out = routBuf + (size_t)cum * 256;
            in = rinBuf + (size_t)cum * 256;
        }
        if (stage == 0)
            in = (l == 0) ? f0 : (l == 1) ? f1 : (l == 2) ? f2 : (l == 3) ? f3 : f4;
    } else {
        relu = 0;
        if (y < 13) {
            ocBase = y * 64; Cout = 819; CoutPad = 896;
            wT = wTc; bias = bc;
            in = cinBuf + (size_t)cum * 256;
            out = coutBuf + (size_t)cum * 819;
        } else {
            ocBase = 0; Cout = 36; CoutPad = 128;
            wT = wTr; bias = br;
            in = rinBuf + (size_t)cum * 256;
            out = routBuf + (size_t)cum * 36;
        }
    }

    int tid = threadIdx.x;
    int tx = tid & 15, ty = tid >> 4;

    int pxF = tid & 63;
    int kB0 = tid >> 6;
    int pF = pxBase + pxF;
    int prow = pF >> logW;
    int pcol = pF & (W - 1);
    bool okp = pF < HW;

    ull acc[8][2];
#pragma unroll
    for (int i = 0; i < 8; i++) { acc[i][0] = 0ull; acc[i][1] = 0ull; }

    float4 pa0, pa1;
    float pb[8];

    int tapCur = -1;
    bool okT = false;
    long bcur = 0;
    const float* wptr = wT + (size_t)(tid >> 4) * CoutPad + ocBase + ((tid & 15) << 2);
    const size_t wInc = (size_t)16 * CoutPad;
    const size_t w8 = (size_t)8 * CoutPad;
    const long bInc = (long)16 * HW;

    auto fetch = [&](int c) {
        int tap = c >> 4;
        if (tap != tapCur) {
            tapCur = tap;
            int dy = tap / 3 - 1, dx = tap % 3 - 1;
            int hh = prow + dy, ww = pcol + dx;
            okT = okp && ((unsigned)hh < (unsigned)W) && ((unsigned)ww < (unsigned)W);
            bcur = (long)kB0 * HW + (((long)hh) << logW) + ww;
        }
#pragma unroll
        for (int i = 0; i < 8; i++)
            pb[i] = okT ? in[bcur + (long)2 * i * HW] : 0.f;
        bcur += bInc;
        pa0 = *(const float4*)(wptr);
        pa1 = *(const float4*)(wptr + w8);
        wptr += wInc;
    };
    auto stor = [&](int buf) {
        float4* asf = (float4*)&As[buf][0][0];
        asf[tid] = pa0;
        asf[128 + tid] = pa1;
#pragma unroll
        for (int i = 0; i < 8; i++) Bs[buf][kB0 + 2 * i][pxF] = pb[i];
    };

    fetch(0);
    stor(0);
    __syncthreads();

    const int NC = 144;
    for (int c = 0; c < NC; c++) {
        int buf = c & 1;
        if (c + 1 < NC) fetch(c + 1);
#pragma unroll
        for (int k = 0; k < 16; k++) {
            float4 a0 = *(const float4*)&As[buf][k][ty << 3];
            float4 a1 = *(const float4*)&As[buf][k][(ty << 3) + 4];
            ulonglong2 b01 = *(const ulonglong2*)&Bs[buf][k][tx << 2];
            float av[8] = {a0.x, a0.y, a0.z, a0.w, a1.x, a1.y, a1.z, a1.w};
#pragma unroll
            for (int i = 0; i < 8; i++) {
                ull aa = pk2(av[i], av[i]);
                ffma2(acc[i][0], aa, b01.x);
                ffma2(acc[i][1], aa, b01.y);
            }
        }
        if (c + 1 < NC) stor(buf ^ 1);
        __syncthreads();
    }

#pragma unroll
    for (int i = 0; i < 8; i++) {
        int oc = ocBase + (ty << 3) + i;
        if (oc >= Cout) continue;
        float bvl = bias[oc];
        size_t ob = (size_t)oc * HW;
#pragma unroll
        for (int j = 0; j < 2; j++) {
            float lo, hi;
            unpk2(acc[i][j], lo, hi);
            int px = pxBase + (tx << 2) + 2 * j;
            if (px < HW) {
                float v = lo + bvl;
                if (relu) v = fmaxf(v, 0.f);
                out[ob + px] = v;
            }
            if (px + 1 < HW) {
                float v = hi + bvl;
                if (relu) v = fmaxf(v, 0.f);
                out[ob + px + 1] = v;
            }
        }
    }
}

// ------------- fused keys + direct compaction (memory-order, logit pre-filter) -------------
// grid (128, 5). Exact: lg <= LOGIT_PREF provably implies s < 0.05 (gap >> expf error).
__global__ void keys_compact_kernel(const float* __restrict__ LOG, unsigned* __restrict__ keys,
                                    unsigned* __restrict__ ck, int* __restrict__ ci) {
    int lvl = blockIdx.y;
    int HW = c_HW[lvl];
    int logHW = c_logHW[lvl];
    int total = 819 << logHW;
    const float* lg0 = LOG + (size_t)c_cumHW[lvl] * 819;
    unsigned* kk = keys + c_KB[lvl];
    unsigned* ckL = ck + lvl * SCAP;
    int* ciL = ci + lvl * SCAP;
    int stride = gridDim.x * blockDim.x;
    for (int idx = blockIdx.x * blockDim.x + threadIdx.x; idx < total; idx += stride) {
        int ch = idx >> logHW;
        int p = idx & (HW - 1);
        float lg = lg0[idx];
        unsigned k = 0u;
        if (lg > LOGIT_PREF) {
            float s = 1.f / (1.f + expf(-lg));
            if (s > 0.05f) k = __float_as_uint(s);
        }
        int i = p * 819 + ch;
        kk[i] = k;
        if (k) {
            int pos = atomicAdd(&d_st[lvl].cnt, 1);
            if (pos < SCAP) { ckL[pos] = k; ciL[pos] = i; }
        }
    }
}

// grid (5), 1024 threads, 64KB dyn smem: bitonic over dynamic pow2 >= max(M,1024)
__global__ void sort_kernel(const unsigned* __restrict__ ck, const int* __restrict__ ci,
                            float* __restrict__ slot_s, int* __restrict__ slot_i) {
    extern __shared__ ull s[];
    int lvl = blockIdx.x;
    const unsigned* ckL = ck + lvl * SCAP;
    const int* ciL = ci + lvl * SCAP;
    float* ss = slot_s + lvl * TOPKN;
    int* si = slot_i + lvl * TOPKN;
    int M = d_st[lvl].cnt; if (M > SCAP) M = SCAP;
    int P2 = 1024;
    while (P2 < M) P2 <<= 1;
    for (int i = threadIdx.x; i < P2; i += 1024)
        s[i] = (i < M) ? (((ull)ckL[i] << 32) | (unsigned)(~(unsigned)ciL[i])) : 0ull;
    __syncthreads();
    for (int k = 2; k <= P2; k <<= 1) {
        for (int j = k >> 1; j > 0; j >>= 1) {
            for (int i = threadIdx.x; i < P2; i += 1024) {
                int l2 = i ^ j;
                if (l2 > i) {
                    ull a = s[i], b = s[l2];
                    bool up = ((i & k) == 0);
                    if (up ? (a < b) : (a > b)) { s[i] = b; s[l2] = a; }
                }
            }
            __syncthreads();
        }
    }
    int outn = (M < TOPKN) ? M : TOPKN;
    for (int i = threadIdx.x; i < outn; i += 1024) {
        ull v = s[i];
        ss[i] = __uint_as_float((unsigned)(v >> 32));
        si[i] = (int)(~(unsigned)(v & 0xffffffffull));
    }
    if (threadIdx.x == 0) d_st[lvl].slotn = outn;
}

// grid (5), 1024 threads: fill remaining slots with first failing indices (ascending)
__global__ void fill_kernel(const unsigned* __restrict__ keys,
                            float* __restrict__ slot_s, int* __restrict__ slot_i) {
    __shared__ int scn[1024];
    __shared__ int s_coll;
    int lvl = blockIdx.x;
    int N = c_NL[lvl];
    const unsigned* kk = keys + c_KB[lvl];
    float* ss = slot_s + lvl * TOPKN;
    int* si = slot_i + lvl * TOPKN;
    int m = TOPKN - d_st[lvl].slotn;
    if (m <= 0) return;
    int base = d_st[lvl].slotn;
    if (threadIdx.x == 0) s_coll = 0;
    __syncthreads();
    for (int start = 0; start < N; start += 1024) {
        int collected = s_coll;
        if (collected >= m) break;
        int i = start + threadIdx.x;
        int fail = (i < N && kk[i] == 0u) ? 1 : 0;
        scn[threadIdx.x] = fail;
        __syncthreads();
        for (int d = 1; d < 1024; d <<= 1) {
            int v = scn[threadIdx.x];
            int add = (threadIdx.x >= (unsigned)d) ? scn[threadIdx.x - d] : 0;
            __syncthreads();
            scn[threadIdx.x] = v + add;
            __syncthreads();
        }
        int incl = scn[threadIdx.x];
        int excl = incl - fail;
        if (fail && collected + excl < m) {
            ss[base + collected + excl] = -1.0f;
            si[base + collected + excl] = i;
        }
        __syncthreads();
        if (threadIdx.x == 1023) s_coll = collected + incl;
        __syncthreads();
    }
}

// ------------- decode + clip + global box-max; grid (4,5) -------------
__global__ void decode_kernel(const float* __restrict__ REG, const float* __restrict__ anchors,
                              const float* __restrict__ slot_s, const int* __restrict__ slot_i,
                              float* __restrict__ cand_s, float* __restrict__ cand_b,
                              int* __restrict__ cand_l) {
    int lvl = blockIdx.y;
    int i = blockIdx.x * blockDim.x + threadIdx.x;
    if (i >= TOPKN) return;
    int HW = c_HW[lvl];
    int aOff = c_cumHW[lvl] * 9;
    const float* reg = REG + (size_t)c_cumHW[lvl] * 36;
    float sc = slot_s[lvl * TOPKN + i];
    int idx = slot_i[lvl * TOPKN + i];
    int c = idx % NCLS;
    int r = idx / NCLS;
    int a = r % NANC;
    int p = r / NANC;
    float r0 = reg[(size_t)(a * 4 + 0) * HW + p];
    float r1 = reg[(size_t)(a * 4 + 1) * HW + p];
    float r2 = reg[(size_t)(a * 4 + 2) * HW + p];
    float r3 = reg[(size_t)(a * 4 + 3) * HW + p];
    const float* an = anchors + (size_t)(aOff + r) * 4;
    float ax0 = an[0], ay0 = an[1], ax1 = an[2], ay1 = an[3];
    float w = ax1 - ax0, h = ay1 - ay0;
    float cx = ax0 + 0.5f * w, cy = ay0 + 0.5f * h;
    float dw = fminf(r2, BBOX_CLIP), dh = fminf(r3, BBOX_CLIP);
    float pcx = r0 * w + cx, pcy = r1 * h + cy;
    float pw = expf(dw) * w, ph = expf(dh) * h;
    float x0 = fminf(fmaxf(pcx - 0.5f * pw, 0.f), IMGSZ);
    float y0 = fminf(fmaxf(pcy - 0.5f * ph, 0.f), IMGSZ);
    float x1 = fminf(fmaxf(pcx + 0.5f * pw, 0.f), IMGSZ);
    float y1 = fminf(fmaxf(pcy + 0.5f * ph, 0.f), IMGSZ);
    int o = lvl * TOPKN + i;
    cand_s[o] = sc;
    cand_b[o * 4 + 0] = x0; cand_b[o * 4 + 1] = y0;
    cand_b[o * 4 + 2] = x1; cand_b[o * 4 + 3] = y1;
    cand_l[o] = c;
    float mx = fmaxf(fmaxf(x0, y0), fmaxf(x1, y1));
    atomicMax(&g_gmax, __float_as_int(mx));
}

// ------------- sequential NMS, 1024 threads, 5/thread, early exit when max <= thresh -------
__global__ void nms_kernel(const float* __restrict__ cs, const float* __restrict__ cb,
                           const int* __restrict__ cl, float* __restrict__ out, int out_size) {
    extern __shared__ float sm[];
    float* s0 = sm;
    float* s1 = sm + 5000;
    float* s2 = sm + 10000;
    float* s3 = sm + 15000;
    float* s4 = sm + 20000;
    __shared__ float rv[32];
    __shared__ int ri[32];
    __shared__ float sjv;
    __shared__ int sji;
    __shared__ int s_stop;
    __shared__ int sel[DETSN];
    __shared__ int val[DETSN];
    int t = threadIdx.x;
    float off1 = __int_as_float(g_gmax) + 1.0f;
    float alive[5], b0[5], b1v[5], b2[5], b3[5], ar[5];
#pragma unroll
    for (int k = 0; k < 5; k++) {
        int e = t + k * 1024;
        if (e < 5000) {
            float s = cs[e];
            float o = (float)cl[e] * off1;
            float x0 = cb[e * 4 + 0] + o, y0 = cb[e * 4 + 1] + o;
            float x1 = cb[e * 4 + 2] + o, y1 = cb[e * 4 + 3] + o;
            b0[k] = x0; b1v[k] = y0; b2[k] = x1; b3[k] = y1;
            ar[k] = (x1 - x0) * (y1 - y0);
            s0[e] = x0; s1[e] = y0; s2[e] = x1; s3[e] = y1; s4[e] = ar[k];
            alive[k] = (s > 0.05f) ? s : NEGV;
        } else {
            alive[k] = -3.0e38f;
            b0[k] = b1v[k] = b2[k] = b3[k] = 0.f; ar[k] = 0.f;
        }
    }
    __syncthreads();
    for (int it = 0; it < DETSN; ++it) {
        float bv = -3.4e38f; int bi = 0x7fffffff;
#pragma unroll
        for (int k = 0; k < 5; k++) {
            int e = t + k * 1024;
            float v = alive[k];
            if (v > bv || (v == bv && e < bi)) { bv = v; bi = e; }
        }
        for (int o = 16; o > 0; o >>= 1) {
            float ov = __shfl_down_sync(0xffffffffu, bv, o);
            int oi = __shfl_down_sync(0xffffffffu, bi, o);
            if (ov > bv || (ov == bv && oi < bi)) { bv = ov; bi = oi; }
        }
        if ((t & 31) == 0) { rv[t >> 5] = bv; ri[t >> 5] = bi; }
        __syncthreads();
        if (t < 32) {
            bv = rv[t]; bi = ri[t];
            for (int o = 16; o > 0; o >>= 1) {
                float ov = __shfl_down_sync(0xffffffffu, bv, o);
                int oi = __shfl_down_sync(0xffffffffu, bi, o);
                if (ov > bv || (ov == bv && oi < bi)) { bv = ov; bi = oi; }
            }
            if (t == 0) {
                sjv = bv; sji = bi;
                s_stop = (bv <= 0.05f) ? 1 : 0;
            }
        }
        __syncthreads();
        if (s_stop) {
            // all remaining selections (incl. this one) are invalid -> zeros
            for (int i2 = it + t; i2 < DETSN; i2 += 1024) { sel[i2] = 0; val[i2] = 0; }
            __syncthreads();
            break;
        }
        int j = sji;
        if (t == 0) { sel[it] = j; val[it] = 1; }
        float jx0 = s0[j], jy0 = s1[j], jx1 = s2[j], jy1 = s3[j], ja = s4[j];
#pragma unroll
        for (int k = 0; k < 5; k++) {
            int e = t + k * 1024;
            if (e == j) alive[k] = NEGV;
            float lt0 = fmaxf(jx0, b0[k]), lt1 = fmaxf(jy0, b1v[k]);
            float rb0 = fminf(jx1, b2[k]), rb1 = fminf(jy1, b3[k]);
            float w = fmaxf(rb0 - lt0, 0.f), h = fmaxf(rb1 - lt1, 0.f);
            float inter = w * h;
            float iou = inter / (ja + ar[k] - inter + 1e-12f);
            if (iou > 0.5f) alive[k] = NEGV;
        }
        __syncthreads();
    }
    for (int i = t; i < DETSN; i += 1024) {
        int j = sel[i]; int v = val[i];
        if (i * 5 + 4 < out_size) {
            out[i * 5 + 0] = v ? cs[j] : 0.f;
            out[i * 5 + 1] = v ? cb[j * 4 + 0] : 0.f;
            out[i * 5 + 2] = v ? cb[j * 4 + 1] : 0.f;
            out[i * 5 + 3] = v ? cb[j * 4 + 2] : 0.f;
            out[i * 5 + 4] = v ? cb[j * 4 + 3] : 0.f;
        }
        int li = DETSN * 5 + i;
        if (li < out_size) out[li] = v ? (float)cl[j] : -1.0f;
    }
    for (int i = DETSN * 6 + t; i < out_size; i += 1024) out[i] = 0.f;
}

extern "C" void kernel_launch(void* const* d_in, const int* in_sizes, int n_in,
                              void* d_out, int out_size) {
    const float* f0 = (const float*)d_in[0];
    const float* f1 = (const float*)d_in[1];
    const float* f2 = (const float*)d_in[2];
    const float* f3 = (const float*)d_in[3];
    const float* f4 = (const float*)d_in[4];
    const float* anchors = (const float*)d_in[5];
    const float* ctw = (const float*)d_in[6];
    const float* ctb = (const float*)d_in[7];
    const float* cow = (const float*)d_in[8];
    const float* cob = (const float*)d_in[9];
    const float* rtw = (const float*)d_in[10];
    const float* rtb = (const float*)d_in[11];
    const float* rbw = (const float*)d_in[12];
    const float* rbb = (const float*)d_in[13];

    float* S = nullptr;
    cudaGetSymbolAddress((void**)&S, g_scratch);
    cudaFuncSetAttribute(sort_kernel, cudaFuncAttributeMaxDynamicSharedMemorySize, SCAP * 8);
    cudaFuncSetAttribute(nms_kernel, cudaFuncAttributeMaxDynamicSharedMemorySize, 100000);

    float* WT_CT = S + OFF_WT_CT;
    float* WT_RT = S + OFF_WT_RT;
    float* WT_CL = S + OFF_WT_CL;
    float* WT_RB = S + OFF_WT_RB;
    float* BUFA = S + OFF_BUFA;
    float* BUFB = S + OFF_BUFB;
    float* BUFC = S + OFF_BUFC;
    float* BUFD = S + OFF_BUFD;
    float* LOG = S + OFF_LOG;
    float* REG = S + OFF_REG;
    unsigned* keys = (unsigned*)(S + OFF_KEYS);
    unsigned* ck = (unsigned*)(S + OFF_CK);
    int* ci = (int*)(S + OFF_CI);
    float* sls = S + OFF_SLS;
    int* sli = (int*)(S + OFF_SLI);
    float* cand_s = S + OFF_CS;
    float* cand_b = S + OFF_CB;
    int* cand_l = (int*)(S + OFF_CL2);

    const size_t TW = 589824;

    transpose_all<<<3072, 256>>>(ctw, rtw, cow, rbw);
    zero_all<<<1, 32>>>();

    dim3 gt(86, 8), gh(86, 14);
    conv_merged<<<gt, 128>>>(f0, f1, f2, f3, f4, nullptr, nullptr,
                             WT_CT + 0 * TW, ctb + 0, BUFA,
                             WT_RT + 0 * TW, rtb + 0, BUFC, 0, 0);
    conv_merged<<<gt, 128>>>(f0, f1, f2, f3, f4, BUFA, BUFC,
                             WT_CT + 1 * TW, ctb + 256, BUFB,
                             WT_RT + 1 * TW, rtb + 256, BUFD, 1, 0);
    conv_merged<<<gt, 128>>>(f0, f1, f2, f3, f4, BUFB, BUFD,
                             WT_CT + 2 * TW, ctb + 512, BUFA,
                             WT_RT + 2 * TW, rtb + 512, BUFC, 2, 0);
    conv_merged<<<gt, 128>>>(f0, f1, f2, f3, f4, BUFA, BUFC,
                             WT_CT + 3 * TW, ctb + 768, BUFB,
                             WT_RT + 3 * TW, rtb + 768, BUFD, 3, 0);
    conv_merged<<<gh, 128>>>(f0, f1, f2, f3, f4, BUFB, BUFD,
                             WT_CL, cob, LOG,
                             WT_RB, rbb, REG, 4, 1);

    keys_compact_kernel<<<dim3(128, 5), 256>>>(LOG, keys, ck, ci);
    sort_kernel<<<5, 1024, SCAP * 8>>>(ck, ci, sls, sli);
    fill_kernel<<<5, 1024>>>(keys, sls, sli);
    decode_kernel<<<dim3(4, 5), 256>>>(REG, anchors, sls, sli, cand_s, cand_b, cand_l);

    nms_kernel<<<1, 1024, 100000>>>(cand_s, cand_b, cand_l, (float*)d_out, out_size);
}